// round 7
// baseline (speedup 1.0000x reference)
#include <cuda_runtime.h>

// Shapes (fixed by the problem)
#define NB   4096          // batch B
#define NP   12            // P = PATCH_NUM - MASK_NUM
#define DIN  640
#define DD   128
#define MP   (NP * NB)     // 49152
#define GBLK (NB / 128)    // 32 CTAs for the global input
#define PBLK (MP / 128)    // 384 CTAs for the patch input
#define INV_T    0.25f     // 1/T, T=4
#define KL_SCALE (16.0f / 128.0f)   // T^2 / D

typedef unsigned long long ull;

// Scratch (device globals: allocation-free rule)
__device__ float d_hg[NB * DD];
__device__ float d_hp[MP * DD];
__device__ float d_g[NB * DD];
__device__ float d_p[MP * DD];
__device__ float d_part_dil[NB];
__device__ float d_part_dcl[NB];

// ---------------------------------------------------------------------------
// Packed f32x2 helpers (SASS: FFMA2 — only reachable via PTX)
// ---------------------------------------------------------------------------
__device__ __forceinline__ ull ffma2(ull a, ull b, ull c)
{
    ull d;
    asm("fma.rn.f32x2 %0, %1, %2, %3;" : "=l"(d) : "l"(a), "l"(b), "l"(c));
    return d;
}
__device__ __forceinline__ ull bcast2(float x)
{
    ull v;
    asm("mov.b64 %0, {%1, %1};" : "=l"(v) : "f"(x));
    return v;
}
__device__ __forceinline__ float2 unpack2(ull v)
{
    float2 r;
    asm("mov.b64 {%0, %1}, %2;" : "=f"(r.x), "=f"(r.y) : "l"(v));
    return r;
}

// ---------------------------------------------------------------------------
// Fused-grid SGEMM: out[m, n] = epi( sum_k A[m,k] * W[n,k] + bias[n] )
// One launch covers BOTH the global (32 CTAs) and patch (384 CTAs) inputs.
// BM=128, BN=128 (full width), BK=16, 512 threads, 4x8 micro-tile per thread
// with packed f32x2 FMAs (pairs along n; n-pairs load free via LDS.128).
// RELU=true  : epilogue = +bias, relu, store
// RELU=false : epilogue = +bias, L2-normalize each row, store
// ---------------------------------------------------------------------------
template <bool RELU>
__global__ __launch_bounds__(512)
void mlp_gemm(const float* __restrict__ Ag, const float* __restrict__ Ap,
              const float* __restrict__ Wg, const float* __restrict__ bg,
              const float* __restrict__ Wp, const float* __restrict__ bp,
              float* __restrict__ outg, float* __restrict__ outp, int K)
{
    const float* A; const float* W; const float* bias; float* out; int m0;
    if (blockIdx.x < GBLK) {
        A = Ag; W = Wg; bias = bg; out = outg; m0 = blockIdx.x * 128;
    } else {
        A = Ap; W = Wp; bias = bp; out = outp; m0 = (blockIdx.x - GBLK) * 128;
    }

    __shared__ float As[16][128];   // [k][m]
    __shared__ float Ws[16][128];   // [k][n]

    const int tid  = threadIdx.x;
    const int tx   = tid & 15;      // n group: cols tx*8 .. tx*8+7
    const int ty   = tid >> 4;      // m group: rows ty*4 .. ty*4+3  (0..31)
    const int lrow = tid >> 2;      // 0..127 (loader row)
    const int kq   = tid & 3;       // which float4 along K

    const float* Apt = A + (m0 + lrow) * K + kq * 4;
    const float* Wpt = W + lrow * K + kq * 4;

    ull acc[4][4];                  // [m row][n pair]
#pragma unroll
    for (int i = 0; i < 4; i++)
#pragma unroll
        for (int j = 0; j < 4; j++) acc[i][j] = 0ULL;

    float4 pa = *(const float4*)(Apt);
    float4 pw = *(const float4*)(Wpt);

    for (int kt = 0; kt < K; kt += 16) {
        __syncthreads();
        As[kq * 4 + 0][lrow] = pa.x;
        As[kq * 4 + 1][lrow] = pa.y;
        As[kq * 4 + 2][lrow] = pa.z;
        As[kq * 4 + 3][lrow] = pa.w;
        Ws[kq * 4 + 0][lrow] = pw.x;
        Ws[kq * 4 + 1][lrow] = pw.y;
        Ws[kq * 4 + 2][lrow] = pw.z;
        Ws[kq * 4 + 3][lrow] = pw.w;
        __syncthreads();

        if (kt + 16 < K) {
            pa = *(const float4*)(Apt + kt + 16);
            pw = *(const float4*)(Wpt + kt + 16);
        }

#pragma unroll
        for (int k = 0; k < 16; k++) {
            const float4 av = *(const float4*)(&As[k][ty * 4]);
            const ulonglong2 bv0 = *(const ulonglong2*)(&Ws[k][tx * 8]);
            const ulonglong2 bv1 = *(const ulonglong2*)(&Ws[k][tx * 8 + 4]);
            ull a2[4], b2[4];
            a2[0] = bcast2(av.x); a2[1] = bcast2(av.y);
            a2[2] = bcast2(av.z); a2[3] = bcast2(av.w);
            b2[0] = bv0.x; b2[1] = bv0.y; b2[2] = bv1.x; b2[3] = bv1.y;
#pragma unroll
            for (int i = 0; i < 4; i++)
#pragma unroll
                for (int j = 0; j < 4; j++)
                    acc[i][j] = ffma2(a2[i], b2[j], acc[i][j]);
        }
    }

    // epilogue
    float bv[8];
#pragma unroll
    for (int j = 0; j < 8; j++) bv[j] = bias[tx * 8 + j];

#pragma unroll
    for (int i = 0; i < 4; i++) {
        float v[8];
#pragma unroll
        for (int j = 0; j < 4; j++) {
            const float2 f = unpack2(acc[i][j]);
            v[2 * j]     = f.x + bv[2 * j];
            v[2 * j + 1] = f.y + bv[2 * j + 1];
        }
        const int row = m0 + ty * 4 + i;

        if (RELU) {
            float4 o0, o1;
            o0.x = fmaxf(v[0], 0.0f); o0.y = fmaxf(v[1], 0.0f);
            o0.z = fmaxf(v[2], 0.0f); o0.w = fmaxf(v[3], 0.0f);
            o1.x = fmaxf(v[4], 0.0f); o1.y = fmaxf(v[5], 0.0f);
            o1.z = fmaxf(v[6], 0.0f); o1.w = fmaxf(v[7], 0.0f);
            *(float4*)(out + row * DD + tx * 8)     = o0;
            *(float4*)(out + row * DD + tx * 8 + 4) = o1;
        } else {
            float ss = 0.0f;
#pragma unroll
            for (int j = 0; j < 8; j++) ss = fmaf(v[j], v[j], ss);
            // reduce across the 16 lanes sharing ty (xor<16 stays in group)
#pragma unroll
            for (int o = 1; o < 16; o <<= 1)
                ss += __shfl_xor_sync(0xffffffffu, ss, o);
            const float r = rsqrtf(ss);
            float4 o0, o1;
            o0.x = v[0] * r; o0.y = v[1] * r; o0.z = v[2] * r; o0.w = v[3] * r;
            o1.x = v[4] * r; o1.y = v[5] * r; o1.z = v[6] * r; o1.w = v[7] * r;
            *(float4*)(out + row * DD + tx * 8)     = o0;
            *(float4*)(out + row * DD + tx * 8 + 4) = o1;
        }
    }
}

// ---------------------------------------------------------------------------
// Symmetric KL over one D=128 row handled by one warp (4 elems / lane).
// Returns sum_d (p1 - p2) * (l1 - l2)  (== both KL directions summed).
// ---------------------------------------------------------------------------
__device__ __forceinline__ float warp_sum(float v)
{
#pragma unroll
    for (int o = 16; o > 0; o >>= 1) v += __shfl_xor_sync(0xffffffffu, v, o);
    return v;
}
__device__ __forceinline__ float warp_max(float v)
{
#pragma unroll
    for (int o = 16; o > 0; o >>= 1)
        v = fmaxf(v, __shfl_xor_sync(0xffffffffu, v, o));
    return v;
}

__device__ __forceinline__ float sym_kl(const float z1[4], const float z2[4])
{
    float m1 = fmaxf(fmaxf(z1[0], z1[1]), fmaxf(z1[2], z1[3]));
    float m2 = fmaxf(fmaxf(z2[0], z2[1]), fmaxf(z2[2], z2[3]));
    m1 = warp_max(m1);
    m2 = warp_max(m2);
    float e1[4], e2[4], s1 = 0.0f, s2 = 0.0f;
#pragma unroll
    for (int i = 0; i < 4; i++) {
        e1[i] = __expf(z1[i] - m1); s1 += e1[i];
        e2[i] = __expf(z2[i] - m2); s2 += e2[i];
    }
    s1 = warp_sum(s1);
    s2 = warp_sum(s2);
    const float inv1 = 1.0f / s1, inv2 = 1.0f / s2;
    const float c1 = m1 + __logf(s1), c2 = m2 + __logf(s2);
    float c = 0.0f;
#pragma unroll
    for (int i = 0; i < 4; i++) {
        const float l1 = z1[i] - c1;
        const float l2 = z2[i] - c2;
        c += (e1[i] * inv1 - e2[i] * inv2) * (l1 - l2);
    }
    return warp_sum(c);
}

// ---------------------------------------------------------------------------
// Fused loss: one block per b (128 threads = 4 warps).
//  - compute pbar[b] from the 12 p rows (each read from gmem exactly once)
//  - dil term (warp 0), 12 dcl terms (3 per warp)
// Deterministic: fixed assignment, fixed reduction order.
// ---------------------------------------------------------------------------
__global__ __launch_bounds__(128) void loss_kernel()
{
    __shared__ float sp[NP][DD];   // 12 p rows
    __shared__ float sg[DD];
    __shared__ float spb[DD];
    __shared__ float wpart[4];

    const int b    = blockIdx.x;
    const int tid  = threadIdx.x;      // == d
    const int w    = tid >> 5;
    const int lane = tid & 31;

    // stage data, compute pbar
    sg[tid] = d_g[b * DD + tid];
    float s = 0.0f;
#pragma unroll
    for (int l = 0; l < NP; l++) {
        const float pv = d_p[(l * NB + b) * DD + tid];
        sp[l][tid] = pv;
        s += pv;
    }
    spb[tid] = s * (1.0f / 12.0f);
    __syncthreads();

    // dcl: warp w handles l = 3w .. 3w+2
    float gv[4], pbv[4];
#pragma unroll
    for (int i = 0; i < 4; i++) {
        gv[i]  = sg[lane + 32 * i];
        pbv[i] = spb[lane + 32 * i];
    }

    float dcl = 0.0f;
#pragma unroll
    for (int t = 0; t < 3; t++) {
        const int l = w * 3 + t;
        float z1[4], z2[4];
#pragma unroll
        for (int i = 0; i < 4; i++) {
            const float pv = sp[l][lane + 32 * i];
            const float t1 = gv[i] - pv;
            const float t2 = pbv[i] - pv;
            z1[i] = t1 * t1 * INV_T;
            z2[i] = t2 * t2 * INV_T;
        }
        dcl += sym_kl(z1, z2);
    }
    if (lane == 0) wpart[w] = dcl * KL_SCALE;

    // dil: warp 0
    if (w == 0) {
        float z1[4], z2[4];
#pragma unroll
        for (int i = 0; i < 4; i++) {
            z1[i] = gv[i] * INV_T;
            z2[i] = pbv[i] * INV_T;
        }
        const float dil = sym_kl(z1, z2) * KL_SCALE;
        if (lane == 0) d_part_dil[b] = dil;
    }
    __syncthreads();

    if (tid == 0)
        d_part_dcl[b] = wpart[0] + wpart[1] + wpart[2] + wpart[3];
}

// ---------------------------------------------------------------------------
// Deterministic final reduction: fixed strided order + fixed tree.
// ---------------------------------------------------------------------------
__global__ __launch_bounds__(256) void finalize_kernel(float* out)
{
    __shared__ float sm[256];
    const int tid = threadIdx.x;

    float s = 0.0f;
    for (int i = tid; i < NB; i += 256) s += d_part_dil[i];
    sm[tid] = s;
    __syncthreads();
    for (int o = 128; o > 0; o >>= 1) {
        if (tid < o) sm[tid] += sm[tid + o];
        __syncthreads();
    }
    if (tid == 0) out[0] = sm[0];
    __syncthreads();

    float s2 = 0.0f;
    for (int i = tid; i < NB; i += 256) s2 += d_part_dcl[i];
    sm[tid] = s2;
    __syncthreads();
    for (int o = 128; o > 0; o >>= 1) {
        if (tid < o) sm[tid] += sm[tid + o];
        __syncthreads();
    }
    if (tid == 0) out[1] = sm[0] * (1.0f / 12.0f);
}

// ---------------------------------------------------------------------------
// Launch
// Inputs (metadata order): ebg, ebp, labelsg, glo_w1, glo_b1, glo_w2, glo_b2,
//                          pat_w1, pat_b1, pat_w2, pat_b2
// ---------------------------------------------------------------------------
extern "C" void kernel_launch(void* const* d_in, const int* in_sizes, int n_in,
                              void* d_out, int out_size)
{
    const float* ebg    = (const float*)d_in[0];
    const float* ebp    = (const float*)d_in[1];
    const float* glo_w1 = (const float*)d_in[3];
    const float* glo_b1 = (const float*)d_in[4];
    const float* glo_w2 = (const float*)d_in[5];
    const float* glo_b2 = (const float*)d_in[6];
    const float* pat_w1 = (const float*)d_in[7];
    const float* pat_b1 = (const float*)d_in[8];
    const float* pat_w2 = (const float*)d_in[9];
    const float* pat_b2 = (const float*)d_in[10];
    float* out = (float*)d_out;

    float *hg, *hp, *g, *p;
    cudaGetSymbolAddress((void**)&hg, d_hg);
    cudaGetSymbolAddress((void**)&hp, d_hp);
    cudaGetSymbolAddress((void**)&g,  d_g);
    cudaGetSymbolAddress((void**)&p,  d_p);

    // Layer 1 (K=640) + ReLU — one grid covers global (32) + patch (384)
    mlp_gemm<true><<<GBLK + PBLK, 512>>>(ebg, ebp, glo_w1, glo_b1,
                                         pat_w1, pat_b1, hg, hp, DIN);
    // Layer 2 (K=128) + bias + L2 normalize
    mlp_gemm<false><<<GBLK + PBLK, 512>>>(hg, hp, glo_w2, glo_b2,
                                          pat_w2, pat_b2, g, p, DD);
    // Fused pbar + dil + dcl
    loss_kernel<<<NB, 128>>>();
    finalize_kernel<<<1, 256>>>(out);
}

// round 8
// speedup vs baseline: 1.9851x; 1.9851x over previous
#include <cuda_runtime.h>

// Shapes (fixed by the problem)
#define NB   4096          // batch B
#define NP   12            // P = PATCH_NUM - MASK_NUM
#define DIN  640
#define DD   128
#define MP   (NP * NB)     // 49152
#define GBLK (NB / 128)    // 32 CTAs for the global input
#define PBLK (MP / 128)    // 384 CTAs for the patch input
#define INV_T    0.25f     // 1/T, T=4
#define KL_SCALE (16.0f / 128.0f)   // T^2 / D

// Scratch (device globals: allocation-free rule)
__device__ float d_hg[NB * DD];
__device__ float d_hp[MP * DD];
__device__ float d_g[NB * DD];
__device__ float d_p[MP * DD];
__device__ float d_part_dil[NB];
__device__ float d_part_dcl[NB];
__device__ unsigned int d_ticket;   // zero-init; self-resets each launch

// ---------------------------------------------------------------------------
// Fused-grid SGEMM: out[m, n] = epi( sum_k A[m,k] * W[n,k] + bias[n] )
// One launch covers BOTH the global (32 CTAs) and patch (384 CTAs) inputs.
// BM=128, N=128 full width, BK=16, 256 threads, 8x8 micro-tile,
// register prefetch of next K-tile. __launch_bounds__(256,2) caps regs at 128
// so 2 CTAs (16 warps) fit per SM.
// RELU=true  : epilogue = +bias, relu, store
// RELU=false : epilogue = +bias, L2-normalize each row, store
// ---------------------------------------------------------------------------
template <bool RELU>
__global__ __launch_bounds__(256, 2)
void mlp_gemm(const float* __restrict__ Ag, const float* __restrict__ Ap,
              const float* __restrict__ Wg, const float* __restrict__ bg,
              const float* __restrict__ Wp, const float* __restrict__ bp,
              float* __restrict__ outg, float* __restrict__ outp, int K)
{
    const float* A; const float* W; const float* bias; float* out; int m0;
    if (blockIdx.x < GBLK) {
        A = Ag; W = Wg; bias = bg; out = outg; m0 = blockIdx.x * 128;
    } else {
        A = Ap; W = Wp; bias = bp; out = outp; m0 = (blockIdx.x - GBLK) * 128;
    }

    __shared__ float As[16][128];   // [k][m]
    __shared__ float Ws[16][128];   // [k][n]

    const int tid  = threadIdx.x;
    const int tx   = tid & 15;      // col group (n)
    const int ty   = tid >> 4;      // row group (m)
    const int lrow = tid >> 2;      // 0..63
    const int kq   = tid & 3;       // 0..3  (which float4 along K)

    const float* Ap0 = A + (m0 + lrow) * K + kq * 4;
    const float* Ap1 = A + (m0 + lrow + 64) * K + kq * 4;
    const float* Wp0 = W + lrow * K + kq * 4;
    const float* Wp1 = W + (lrow + 64) * K + kq * 4;

    float acc[8][8];
#pragma unroll
    for (int i = 0; i < 8; i++)
#pragma unroll
        for (int j = 0; j < 8; j++) acc[i][j] = 0.0f;

    float4 pa0 = *(const float4*)(Ap0);
    float4 pa1 = *(const float4*)(Ap1);
    float4 pw0 = *(const float4*)(Wp0);
    float4 pw1 = *(const float4*)(Wp1);

    for (int kt = 0; kt < K; kt += 16) {
        __syncthreads();
        As[kq * 4 + 0][lrow]      = pa0.x;
        As[kq * 4 + 1][lrow]      = pa0.y;
        As[kq * 4 + 2][lrow]      = pa0.z;
        As[kq * 4 + 3][lrow]      = pa0.w;
        As[kq * 4 + 0][lrow + 64] = pa1.x;
        As[kq * 4 + 1][lrow + 64] = pa1.y;
        As[kq * 4 + 2][lrow + 64] = pa1.z;
        As[kq * 4 + 3][lrow + 64] = pa1.w;
        Ws[kq * 4 + 0][lrow]      = pw0.x;
        Ws[kq * 4 + 1][lrow]      = pw0.y;
        Ws[kq * 4 + 2][lrow]      = pw0.z;
        Ws[kq * 4 + 3][lrow]      = pw0.w;
        Ws[kq * 4 + 0][lrow + 64] = pw1.x;
        Ws[kq * 4 + 1][lrow + 64] = pw1.y;
        Ws[kq * 4 + 2][lrow + 64] = pw1.z;
        Ws[kq * 4 + 3][lrow + 64] = pw1.w;
        __syncthreads();

        if (kt + 16 < K) {
            pa0 = *(const float4*)(Ap0 + kt + 16);
            pa1 = *(const float4*)(Ap1 + kt + 16);
            pw0 = *(const float4*)(Wp0 + kt + 16);
            pw1 = *(const float4*)(Wp1 + kt + 16);
        }

#pragma unroll
        for (int k = 0; k < 16; k++) {
            float ar[8], br[8];
            float4 a0 = *(const float4*)(&As[k][ty * 8]);
            float4 a1 = *(const float4*)(&As[k][ty * 8 + 4]);
            float4 b0 = *(const float4*)(&Ws[k][tx * 8]);
            float4 b1 = *(const float4*)(&Ws[k][tx * 8 + 4]);
            ar[0] = a0.x; ar[1] = a0.y; ar[2] = a0.z; ar[3] = a0.w;
            ar[4] = a1.x; ar[5] = a1.y; ar[6] = a1.z; ar[7] = a1.w;
            br[0] = b0.x; br[1] = b0.y; br[2] = b0.z; br[3] = b0.w;
            br[4] = b1.x; br[5] = b1.y; br[6] = b1.z; br[7] = b1.w;
#pragma unroll
            for (int i = 0; i < 8; i++)
#pragma unroll
                for (int j = 0; j < 8; j++)
                    acc[i][j] = fmaf(ar[i], br[j], acc[i][j]);
        }
    }

    float bv[8];
#pragma unroll
    for (int j = 0; j < 8; j++) bv[j] = bias[tx * 8 + j];

    if (RELU) {
#pragma unroll
        for (int i = 0; i < 8; i++) {
            const int row = m0 + ty * 8 + i;
            float4 v0, v1;
            v0.x = fmaxf(acc[i][0] + bv[0], 0.0f);
            v0.y = fmaxf(acc[i][1] + bv[1], 0.0f);
            v0.z = fmaxf(acc[i][2] + bv[2], 0.0f);
            v0.w = fmaxf(acc[i][3] + bv[3], 0.0f);
            v1.x = fmaxf(acc[i][4] + bv[4], 0.0f);
            v1.y = fmaxf(acc[i][5] + bv[5], 0.0f);
            v1.z = fmaxf(acc[i][6] + bv[6], 0.0f);
            v1.w = fmaxf(acc[i][7] + bv[7], 0.0f);
            *(float4*)(out + row * DD + tx * 8)     = v0;
            *(float4*)(out + row * DD + tx * 8 + 4) = v1;
        }
    } else {
#pragma unroll
        for (int i = 0; i < 8; i++)
#pragma unroll
            for (int j = 0; j < 8; j++) acc[i][j] += bv[j];

        float ss[8];
#pragma unroll
        for (int i = 0; i < 8; i++) {
            float s = 0.0f;
#pragma unroll
            for (int j = 0; j < 8; j++) s = fmaf(acc[i][j], acc[i][j], s);
            ss[i] = s;
        }
        // reduce across the 16 lanes sharing ty (xor < 16 stays in half-warp)
#pragma unroll
        for (int o = 1; o < 16; o <<= 1) {
#pragma unroll
            for (int i = 0; i < 8; i++)
                ss[i] += __shfl_xor_sync(0xffffffffu, ss[i], o);
        }
#pragma unroll
        for (int i = 0; i < 8; i++) {
            const int row = m0 + ty * 8 + i;
            const float r = rsqrtf(ss[i]);
            float4 v0, v1;
            v0.x = acc[i][0] * r; v0.y = acc[i][1] * r;
            v0.z = acc[i][2] * r; v0.w = acc[i][3] * r;
            v1.x = acc[i][4] * r; v1.y = acc[i][5] * r;
            v1.z = acc[i][6] * r; v1.w = acc[i][7] * r;
            *(float4*)(out + row * DD + tx * 8)     = v0;
            *(float4*)(out + row * DD + tx * 8 + 4) = v1;
        }
    }
}

// ---------------------------------------------------------------------------
// Symmetric KL over one D=128 row handled by one warp (4 elems / lane).
// Returns sum_d (p1 - p2) * (l1 - l2)  (== both KL directions summed).
// ---------------------------------------------------------------------------
__device__ __forceinline__ float warp_sum(float v)
{
#pragma unroll
    for (int o = 16; o > 0; o >>= 1) v += __shfl_xor_sync(0xffffffffu, v, o);
    return v;
}
__device__ __forceinline__ float warp_max(float v)
{
#pragma unroll
    for (int o = 16; o > 0; o >>= 1)
        v = fmaxf(v, __shfl_xor_sync(0xffffffffu, v, o));
    return v;
}

__device__ __forceinline__ float sym_kl(const float z1[4], const float z2[4])
{
    float m1 = fmaxf(fmaxf(z1[0], z1[1]), fmaxf(z1[2], z1[3]));
    float m2 = fmaxf(fmaxf(z2[0], z2[1]), fmaxf(z2[2], z2[3]));
    m1 = warp_max(m1);
    m2 = warp_max(m2);
    float e1[4], e2[4], s1 = 0.0f, s2 = 0.0f;
#pragma unroll
    for (int i = 0; i < 4; i++) {
        e1[i] = __expf(z1[i] - m1); s1 += e1[i];
        e2[i] = __expf(z2[i] - m2); s2 += e2[i];
    }
    s1 = warp_sum(s1);
    s2 = warp_sum(s2);
    const float inv1 = 1.0f / s1, inv2 = 1.0f / s2;
    const float c1 = m1 + __logf(s1), c2 = m2 + __logf(s2);
    float c = 0.0f;
#pragma unroll
    for (int i = 0; i < 4; i++) {
        const float l1 = z1[i] - c1;
        const float l2 = z2[i] - c2;
        c += (e1[i] * inv1 - e2[i] * inv2) * (l1 - l2);
    }
    return warp_sum(c);
}

// ---------------------------------------------------------------------------
// Fused loss: one block per b (128 threads = 4 warps).
//  - pbar[b] from the 12 p rows (each read from gmem exactly once)
//  - dil (warp 0), 12 dcl terms (3 per warp)
//  - LAST finished block performs the final reduction (fixed order ->
//    deterministic), writing out[0] = dil, out[1] = dcl.
// ---------------------------------------------------------------------------
__global__ __launch_bounds__(128) void loss_kernel(float* __restrict__ out)
{
    __shared__ float sp[NP][DD];   // 12 p rows
    __shared__ float sg[DD];
    __shared__ float spb[DD];
    __shared__ float wpart[4];
    __shared__ int   amLast;

    const int b    = blockIdx.x;
    const int tid  = threadIdx.x;      // == d
    const int w    = tid >> 5;
    const int lane = tid & 31;

    // stage data, compute pbar
    sg[tid] = d_g[b * DD + tid];
    float s = 0.0f;
#pragma unroll
    for (int l = 0; l < NP; l++) {
        const float pv = d_p[(l * NB + b) * DD + tid];
        sp[l][tid] = pv;
        s += pv;
    }
    spb[tid] = s * (1.0f / 12.0f);
    __syncthreads();

    // dcl: warp w handles l = 3w .. 3w+2
    float gv[4], pbv[4];
#pragma unroll
    for (int i = 0; i < 4; i++) {
        gv[i]  = sg[lane + 32 * i];
        pbv[i] = spb[lane + 32 * i];
    }

    float dcl = 0.0f;
#pragma unroll
    for (int t = 0; t < 3; t++) {
        const int l = w * 3 + t;
        float z1[4], z2[4];
#pragma unroll
        for (int i = 0; i < 4; i++) {
            const float pv = sp[l][lane + 32 * i];
            const float t1 = gv[i] - pv;
            const float t2 = pbv[i] - pv;
            z1[i] = t1 * t1 * INV_T;
            z2[i] = t2 * t2 * INV_T;
        }
        dcl += sym_kl(z1, z2);
    }
    if (lane == 0) wpart[w] = dcl * KL_SCALE;

    // dil: warp 0
    if (w == 0) {
        float z1[4], z2[4];
#pragma unroll
        for (int i = 0; i < 4; i++) {
            z1[i] = gv[i] * INV_T;
            z2[i] = pbv[i] * INV_T;
        }
        const float dil = sym_kl(z1, z2) * KL_SCALE;
        if (lane == 0) d_part_dil[b] = dil;
    }
    __syncthreads();

    if (tid == 0) {
        d_part_dcl[b] = wpart[0] + wpart[1] + wpart[2] + wpart[3];
        __threadfence();
        amLast = (atomicAdd(&d_ticket, 1u) == (unsigned)(NB - 1));
    }
    __syncthreads();

    // Final reduction by the last-finishing block. Fixed accumulation order
    // (strided per-thread, then fixed tree) -> bitwise deterministic.
    if (amLast) {
        __shared__ float r1[128], r2[128];
        float a = 0.0f, c = 0.0f;
        for (int i = tid; i < NB; i += 128) {
            a += d_part_dil[i];
            c += d_part_dcl[i];
        }
        r1[tid] = a; r2[tid] = c;
        __syncthreads();
        for (int o = 64; o > 0; o >>= 1) {
            if (tid < o) { r1[tid] += r1[tid + o]; r2[tid] += r2[tid + o]; }
            __syncthreads();
        }
        if (tid == 0) {
            out[0] = r1[0];
            out[1] = r2[0] * (1.0f / 12.0f);
            d_ticket = 0;   // reset for next graph replay
        }
    }
}

// ---------------------------------------------------------------------------
// Launch
// Inputs (metadata order): ebg, ebp, labelsg, glo_w1, glo_b1, glo_w2, glo_b2,
//                          pat_w1, pat_b1, pat_w2, pat_b2
// ---------------------------------------------------------------------------
extern "C" void kernel_launch(void* const* d_in, const int* in_sizes, int n_in,
                              void* d_out, int out_size)
{
    const float* ebg    = (const float*)d_in[0];
    const float* ebp    = (const float*)d_in[1];
    const float* glo_w1 = (const float*)d_in[3];
    const float* glo_b1 = (const float*)d_in[4];
    const float* glo_w2 = (const float*)d_in[5];
    const float* glo_b2 = (const float*)d_in[6];
    const float* pat_w1 = (const float*)d_in[7];
    const float* pat_b1 = (const float*)d_in[8];
    const float* pat_w2 = (const float*)d_in[9];
    const float* pat_b2 = (const float*)d_in[10];
    float* out = (float*)d_out;

    float *hg, *hp, *g, *p;
    cudaGetSymbolAddress((void**)&hg, d_hg);
    cudaGetSymbolAddress((void**)&hp, d_hp);
    cudaGetSymbolAddress((void**)&g,  d_g);
    cudaGetSymbolAddress((void**)&p,  d_p);

    // Layer 1 (K=640) + ReLU — one grid covers global (32) + patch (384)
    mlp_gemm<true><<<GBLK + PBLK, 256>>>(ebg, ebp, glo_w1, glo_b1,
                                         pat_w1, pat_b1, hg, hp, DIN);
    // Layer 2 (K=128) + bias + L2 normalize
    mlp_gemm<false><<<GBLK + PBLK, 256>>>(hg, hp, glo_w2, glo_b2,
                                          pat_w2, pat_b2, g, p, DD);
    // Fused pbar + dil + dcl + final reduction (last block)
    loss_kernel<<<NB, 128>>>(out);
}